// round 8
// baseline (speedup 1.0000x reference)
#include <cuda_runtime.h>
#include <cuda_bf16.h>
#include <cstdint>

// Embedding_78666620994160
// out[t, e] = (W[e, ids[t]] + b[e]) * sqrt(512)
// ids: [8*4096] int32, W: [512, 50257] f32, b: [512] f32 -> out [32768,512] f32
//
// v7: ONE persistent kernel, 2 grid barriers:
//   hist (blocks 0-63) -> bar0 -> per-block local scan + scatter (blocks 0-63,
//   monotonic per-bucket counters, no 2nd scan barrier) -> bar1 ->
//   dynamic-queue transposed gather (no tail quantization).
// All sync state is epoch-monotonic => graph-replay safe, no resets.

#define VOCAB    50257
#define EMB      512
#define N_TOKENS (8 * 4096)
#define BUCKET_SHIFT 5
#define NBINS_PAD 2048

#define NBLK 592                 // 148 SMs x occ 4
#define NTHR 512
#define TOK_PER_BLK 32
#define E4_PER_BLK  64
#define S4_PITCH    65
#define NTILES ((N_TOKENS / TOK_PER_BLK) * 2)   // 2048
#define GRABS_PER_LAUNCH (NTILES + NBLK)        // exact queue use per launch

__device__ int          g_hist2[2][NBINS_PAD]; // parity ping-pong, re-zeroed in-kernel
__device__ int          g_cnt2[NBINS_PAD];     // monotonic per-bucket scatter counters
__device__ int2         g_sorted[N_TOKENS];
__device__ unsigned int g_tile = 0;            // monotonic gather work queue

__device__ volatile int g_bar0 = 0;
__device__ volatile int g_bar1 = 0;
__device__ int          g_epoch = 0;

__device__ __forceinline__ void grid_bar(volatile int* ctr, int e0)
{
    __threadfence();
    __syncthreads();
    if (threadIdx.x == 0) {
        atomicAdd((int*)ctr, 1);
        const int target = e0 * NBLK + NBLK;
        while (*ctr < target) __nanosleep(32);
    }
    __syncthreads();
    __threadfence();
}

__global__ void __launch_bounds__(NTHR, 4)
emb_fused_kernel(const int* __restrict__ ids,
                 const float* __restrict__ W,
                 const float* __restrict__ b,
                 float* __restrict__ out)
{
    const float SCALE = 22.62741699796952f; // sqrt(512)
    __shared__ float4   S4[TOK_PER_BLK * S4_PITCH];
    __shared__ int      sb[NBINS_PAD];      // per-block scatter bases
    __shared__ int      wsum[16];
    __shared__ unsigned s_tile;

    const int tid = threadIdx.x;
    const int e0  = g_epoch;                // stable across this launch
    const int par = e0 & 1;
    const int gtid = blockIdx.x * NTHR + tid;

    // ---- Phase A: histogram (blocks 0..63 own the 32768 tokens) ----
    int id = 0;
    if (blockIdx.x < 64) {
        id = __ldg(&ids[gtid]);
        atomicAdd(&g_hist2[par][id >> BUCKET_SHIFT], 1);  // REDG (no return)
    }
    grid_bar(&g_bar0, e0);

    // ---- Phase B: local scan + scatter (token-owning blocks only) ----
    if (blockIdx.x < 64) {
        const int lane = tid & 31, wid = tid >> 5;
        const int base = tid * 4;
        int v0 = g_hist2[par][base + 0];
        int v1 = g_hist2[par][base + 1];
        int v2 = g_hist2[par][base + 2];
        int v3 = g_hist2[par][base + 3];
        int s  = v0 + v1 + v2 + v3;

        int x = s;
        #pragma unroll
        for (int off = 1; off < 32; off <<= 1) {
            int y = __shfl_up_sync(0xffffffffu, x, off);
            if (lane >= off) x += y;
        }
        if (lane == 31) wsum[wid] = x;
        __syncthreads();
        if (wid == 0 && lane < 16) {
            int w = wsum[lane];
            int xw = w;
            #pragma unroll
            for (int off = 1; off < 16; off <<= 1) {
                int y = __shfl_up_sync(0x0000ffffu, xw, off);
                if (lane >= off) xw += y;
            }
            wsum[lane] = xw - w;
        }
        __syncthreads();

        int run = wsum[wid] + (x - s);       // exclusive prefix of bin 'base'
        // base_adj = prefix - e0*count  (g_cnt2 is monotonic across launches)
        sb[base + 0] = run - e0 * v0;   run += v0;
        sb[base + 1] = run - e0 * v1;   run += v1;
        sb[base + 2] = run - e0 * v2;   run += v2;
        sb[base + 3] = run - e0 * v3;
        __syncthreads();

        int bkt = id >> BUCKET_SHIFT;
        int pos = sb[bkt] + atomicAdd(&g_cnt2[bkt], 1);
        __stcs(&g_sorted[pos], make_int2(gtid, id));
    }
    grid_bar(&g_bar1, e0);

    // ---- housekeeping (all hist readers are done) ----
    if (blockIdx.x == 64) {                  // re-zero this parity's histogram
        int i4 = tid * 4;
        g_hist2[par][i4 + 0] = 0;
        g_hist2[par][i4 + 1] = 0;
        g_hist2[par][i4 + 2] = 0;
        g_hist2[par][i4 + 3] = 0;
    }
    if (blockIdx.x == 0 && tid == 0) g_epoch = e0 + 1;

    // ---- Phase C: dynamic-queue transposed gather ----
    const unsigned qbase = (unsigned)e0 * GRABS_PER_LAUNCH;
    const int t  = tid & 31;                 // gather lane = local token
    const int ty = tid >> 5;                 // 0..15
    const int tl = tid >> 4;                 // 0..31 (store phase token)
    const int ey = tid & 15;                 // 0..15 (store phase e4)

    for (;;) {
        if (tid == 0) s_tile = atomicAdd(&g_tile, 1u) - qbase;  // one grab/iter
        __syncthreads();
        unsigned tile = s_tile;
        if (tile >= NTILES) break;           // each block: exactly 1 terminal grab

        int tg     = (int)(tile >> 1);       // token group of 32
        int e4base = (int)(tile & 1) * E4_PER_BLK;

        int sid = g_sorted[tg * TOK_PER_BLK + t].y;

        #pragma unroll
        for (int i = 0; i < 4; i++) {
            int e4l = ty + 16 * i;
            int e4g = e4base + e4l;
            float4 bv = __ldg((const float4*)b + e4g);
            const float* wp = W + (size_t)(4 * e4g) * VOCAB + sid;
            float4 r;
            r.x = (__ldg(wp)                     + bv.x) * SCALE;
            r.y = (__ldg(wp + (size_t)VOCAB)     + bv.y) * SCALE;
            r.z = (__ldg(wp + (size_t)2 * VOCAB) + bv.z) * SCALE;
            r.w = (__ldg(wp + (size_t)3 * VOCAB) + bv.w) * SCALE;
            S4[t * S4_PITCH + e4l] = r;
        }
        __syncthreads();

        int token = g_sorted[tg * TOK_PER_BLK + tl].x;
        float4* outp = (float4*)out + (size_t)token * (EMB / 4) + e4base;
        #pragma unroll
        for (int i = 0; i < 4; i++) {
            int e4l = ey + 16 * i;
            __stcs(&outp[e4l], S4[tl * S4_PITCH + e4l]);
        }
        __syncthreads();                     // S4 + s_tile reuse
    }
}

extern "C" void kernel_launch(void* const* d_in, const int* in_sizes, int n_in,
                              void* d_out, int out_size)
{
    const int*   ids = (const int*)d_in[0];    // [32768] int32
    const float* W   = (const float*)d_in[1];  // [512*50257]
    const float* b   = (const float*)d_in[2];  // [512]
    float*       out = (float*)d_out;          // [32768*512]

    emb_fused_kernel<<<NBLK, NTHR>>>(ids, W, b, out);
}

// round 9
// speedup vs baseline: 1.1875x; 1.1875x over previous
#include <cuda_runtime.h>
#include <cuda_bf16.h>
#include <cstdint>

// Embedding_78666620994160
// out[t, e] = (W[e, ids[t]] + b[e]) * sqrt(512)
// ids: [8*4096] int32, W: [512, 50257] f32, b: [512] f32 -> out [32768,512] f32
//
// v8: back to separate kernels (fusion proven slower in R7/R8):
//   K1 hist -> K2 fused local-scan+scatter (monotonic per-bucket counters,
//   epoch-adjusted bases; no grid barrier) -> K3 transposed gather (proven
//   28.3us config) which also zeroes the hist + bumps the epoch for replay.

#define VOCAB    50257
#define EMB      512
#define N_TOKENS (8 * 4096)
#define BUCKET_SHIFT 5
#define NBINS_PAD 2048

#define TOK_PER_BLK 32
#define E4_PER_BLK  64
#define S4_PITCH    65

__device__ int  g_hist[NBINS_PAD];   // zeroed at load; gather re-zeroes each launch
__device__ int  g_cnt[NBINS_PAD];    // monotonic per-bucket scatter counters
__device__ int2 g_sorted[N_TOKENS];  // (token, id) bucket-sorted
__device__ int  g_epoch = 0;         // completed launches; gather increments

// ---- K1: histogram (64 blocks x 512, 1 token/thread) ----
__global__ void __launch_bounds__(512, 4)
hist_kernel(const int* __restrict__ ids)
{
    int t = blockIdx.x * 512 + threadIdx.x;
    atomicAdd(&g_hist[__ldg(&ids[t]) >> BUCKET_SHIFT], 1);
}

// ---- K2: fused local scan + scatter (64 blocks x 512) ----
// Each block redundantly scans all 2048 bins (cheap, parallel across blocks),
// builds epoch-adjusted bases in smem, then scatters its 512 tokens.
__global__ void __launch_bounds__(512, 2)
scan_scatter_kernel(const int* __restrict__ ids)
{
    __shared__ int sb[NBINS_PAD];
    __shared__ int wsum[16];

    const int tid  = threadIdx.x;
    const int lane = tid & 31, wid = tid >> 5;
    const int e0   = g_epoch;                 // stable (only gather modifies it)

    // local scan: 4 bins/thread
    const int base = tid * 4;
    int v0 = g_hist[base + 0];
    int v1 = g_hist[base + 1];
    int v2 = g_hist[base + 2];
    int v3 = g_hist[base + 3];
    int s  = v0 + v1 + v2 + v3;

    int x = s;
    #pragma unroll
    for (int off = 1; off < 32; off <<= 1) {
        int y = __shfl_up_sync(0xffffffffu, x, off);
        if (lane >= off) x += y;
    }
    if (lane == 31) wsum[wid] = x;
    __syncthreads();
    if (wid == 0 && lane < 16) {
        int w = wsum[lane];
        int xw = w;
        #pragma unroll
        for (int off = 1; off < 16; off <<= 1) {
            int y = __shfl_up_sync(0x0000ffffu, xw, off);
            if (lane >= off) xw += y;
        }
        wsum[lane] = xw - w;                   // exclusive warp base
    }
    __syncthreads();

    int run = wsum[wid] + (x - s);             // exclusive prefix of bin 'base'
    // base adjusted for monotonic counters: g_cnt[b] == e0*count[b] at entry
    sb[base + 0] = run - e0 * v0;   run += v0;
    sb[base + 1] = run - e0 * v1;   run += v1;
    sb[base + 2] = run - e0 * v2;   run += v2;
    sb[base + 3] = run - e0 * v3;
    __syncthreads();

    // scatter this block's 512 tokens
    int t   = blockIdx.x * 512 + tid;
    int id  = __ldg(&ids[t]);
    int bkt = id >> BUCKET_SHIFT;
    int pos = sb[bkt] + atomicAdd(&g_cnt[bkt], 1);
    __stcs(&g_sorted[pos], make_int2(t, id));
}

// ---- K3: transposed gather (proven v4 config) + housekeeping ----
// Block tile: 32 sorted tokens x 64 float4. blockDim=(32,16).
// Phase 1: lane = token -> warp gather hits few 32B sectors (sorted ids).
// Phase 2: coalesced float4 streaming stores, token-major.
__global__ void __launch_bounds__(512, 4)
emb_gather_tr_kernel(const float* __restrict__ W,
                     const float* __restrict__ b,
                     float* __restrict__ out)
{
    const float SCALE = 22.62741699796952f; // sqrt(512)
    __shared__ float4 S4[TOK_PER_BLK * S4_PITCH];

    // housekeeping: block (0,0) zeroes hist (scan already consumed it) and
    // bumps the epoch for the next graph replay.
    if (blockIdx.x == 0 && blockIdx.y == 0) {
        int tid = threadIdx.y * 32 + threadIdx.x;
        int i4 = tid * 4;
        g_hist[i4 + 0] = 0;
        g_hist[i4 + 1] = 0;
        g_hist[i4 + 2] = 0;
        g_hist[i4 + 3] = 0;
        if (tid == 0) g_epoch += 1;
    }

    int t  = threadIdx.x;                        // 0..31 local token
    int ty = threadIdx.y;                        // 0..15
    int s  = blockIdx.x * TOK_PER_BLK + t;       // sorted position
    int e4base = blockIdx.y * E4_PER_BLK;        // global float4 offset

    int id = __ldg(&g_sorted[s]).y;

    // Phase 1: gather 4 e4-slots per thread
    #pragma unroll
    for (int i = 0; i < 4; i++) {
        int e4l = ty + 16 * i;                   // 0..63 local
        int e4g = e4base + e4l;
        float4 bv = __ldg((const float4*)b + e4g);
        const float* wp = W + (size_t)(4 * e4g) * VOCAB + id;
        float4 r;
        r.x = (__ldg(wp)                      + bv.x) * SCALE;
        r.y = (__ldg(wp + (size_t)VOCAB)      + bv.y) * SCALE;
        r.z = (__ldg(wp + (size_t)2 * VOCAB)  + bv.z) * SCALE;
        r.w = (__ldg(wp + (size_t)3 * VOCAB)  + bv.w) * SCALE;
        S4[t * S4_PITCH + e4l] = r;
    }

    __syncthreads();

    // Phase 2: token-major coalesced float4 streaming stores
    int tid  = ty * 32 + t;                      // 0..511
    int tl   = tid >> 4;                         // 0..31 local token
    int ey   = tid & 15;                         // 0..15
    int token = __ldg(&g_sorted[blockIdx.x * TOK_PER_BLK + tl]).x;
    float4* outp = (float4*)out + (size_t)token * (EMB / 4) + e4base;
    #pragma unroll
    for (int i = 0; i < 4; i++) {
        int e4l = ey + 16 * i;
        __stcs(&outp[e4l], S4[tl * S4_PITCH + e4l]);
    }
}

extern "C" void kernel_launch(void* const* d_in, const int* in_sizes, int n_in,
                              void* d_out, int out_size)
{
    const int*   ids = (const int*)d_in[0];    // [32768] int32
    const float* W   = (const float*)d_in[1];  // [512*50257]
    const float* b   = (const float*)d_in[2];  // [512]
    float*       out = (float*)d_out;          // [32768*512]

    hist_kernel<<<N_TOKENS / 512, 512>>>(ids);
    scan_scatter_kernel<<<N_TOKENS / 512, 512>>>(ids);

    dim3 block(32, 16, 1);
    dim3 grid(N_TOKENS / TOK_PER_BLK, EMB / (4 * E4_PER_BLK), 1);  // 1024 x 2
    emb_gather_tr_kernel<<<grid, block>>>(W, b, out);
}

// round 10
// speedup vs baseline: 1.1893x; 1.0015x over previous
#include <cuda_runtime.h>
#include <cuda_bf16.h>
#include <cstdint>

// Embedding_78666620994160
// out[t, e] = (W[e, ids[t]] + b[e]) * sqrt(512)
// ids: [8*4096] int32, W: [512, 50257] f32, b: [512] f32 -> out [32768,512] f32
//
// v9: two kernels.
//   K1 (64 blocks): hist -> 64-block grid barrier -> per-block local scan ->
//      scatter (monotonic per-bucket counters, epoch-adjusted bases).
//   K2: transposed gather (proven 28.3us config); block(0,0) zeroes hist and
//      bumps the epoch for the next graph replay.
// All sync state epoch-monotonic => graph-replay safe, no resets needed.

#define VOCAB    50257
#define EMB      512
#define N_TOKENS (8 * 4096)
#define BUCKET_SHIFT 5
#define NBINS_PAD 2048

#define SORT_BLOCKS 64
#define TOK_PER_BLK 32
#define E4_PER_BLK  64
#define S4_PITCH    65

__device__ int  g_hist[NBINS_PAD];   // zeroed at load; gather re-zeroes each launch
__device__ int  g_cnt[NBINS_PAD];    // monotonic per-bucket scatter counters
__device__ int2 g_sorted[N_TOKENS];  // (token, id) bucket-sorted
__device__ int  g_epoch = 0;         // completed launches; gather increments
__device__ volatile int g_bar = 0;   // monotonic barrier counter

// ---- K1: fused hist + barrier + local scan + scatter (64 blocks x 512) ----
__global__ void __launch_bounds__(512, 2)
sort_kernel(const int* __restrict__ ids)
{
    __shared__ int sb[NBINS_PAD];
    __shared__ int wsum[16];

    const int tid  = threadIdx.x;
    const int lane = tid & 31, wid = tid >> 5;
    const int e0   = g_epoch;               // stable (only gather modifies it)

    // Phase A: histogram (1 token/thread, device-scope atomic -> L2)
    const int t  = blockIdx.x * 512 + tid;
    const int id = __ldg(&ids[t]);
    atomicAdd(&g_hist[id >> BUCKET_SHIFT], 1);

    // 64-block grid barrier (all blocks co-resident: 64 << 148 SMs)
    __threadfence();
    __syncthreads();
    if (tid == 0) {
        atomicAdd((int*)&g_bar, 1);
        const int target = e0 * SORT_BLOCKS + SORT_BLOCKS;
        while (g_bar < target) __nanosleep(32);
    }
    __syncthreads();
    __threadfence();

    // Phase B: local scan of 2048 bins (4/thread), redundant per block
    const int base = tid * 4;
    int v0 = g_hist[base + 0];
    int v1 = g_hist[base + 1];
    int v2 = g_hist[base + 2];
    int v3 = g_hist[base + 3];
    int s  = v0 + v1 + v2 + v3;

    int x = s;
    #pragma unroll
    for (int off = 1; off < 32; off <<= 1) {
        int y = __shfl_up_sync(0xffffffffu, x, off);
        if (lane >= off) x += y;
    }
    if (lane == 31) wsum[wid] = x;
    __syncthreads();
    if (wid == 0 && lane < 16) {
        int w = wsum[lane];
        int xw = w;
        #pragma unroll
        for (int off = 1; off < 16; off <<= 1) {
            int y = __shfl_up_sync(0x0000ffffu, xw, off);
            if (lane >= off) xw += y;
        }
        wsum[lane] = xw - w;                 // exclusive warp base
    }
    __syncthreads();

    int run = wsum[wid] + (x - s);           // exclusive prefix of bin 'base'
    // bases adjusted for monotonic counters: g_cnt[b] == e0*count[b] at entry
    sb[base + 0] = run - e0 * v0;   run += v0;
    sb[base + 1] = run - e0 * v1;   run += v1;
    sb[base + 2] = run - e0 * v2;   run += v2;
    sb[base + 3] = run - e0 * v3;
    __syncthreads();

    // Phase C: scatter this block's 512 tokens
    int bkt = id >> BUCKET_SHIFT;
    int pos = sb[bkt] + atomicAdd(&g_cnt[bkt], 1);
    __stcs(&g_sorted[pos], make_int2(t, id));
}

// ---- K2: transposed gather (proven config) + housekeeping ----
// Block tile: 32 sorted tokens x 64 float4. blockDim=(32,16).
// Phase 1: lane = token -> warp gather hits few 32B sectors (sorted ids).
// Phase 2: coalesced float4 streaming stores, token-major.
__global__ void __launch_bounds__(512, 4)
emb_gather_tr_kernel(const float* __restrict__ W,
                     const float* __restrict__ b,
                     float* __restrict__ out)
{
    const float SCALE = 22.62741699796952f; // sqrt(512)
    __shared__ float4 S4[TOK_PER_BLK * S4_PITCH];

    // housekeeping: block (0,0) zeroes hist (already consumed) and bumps epoch
    if (blockIdx.x == 0 && blockIdx.y == 0) {
        int tid = threadIdx.y * 32 + threadIdx.x;
        int i4 = tid * 4;
        g_hist[i4 + 0] = 0;
        g_hist[i4 + 1] = 0;
        g_hist[i4 + 2] = 0;
        g_hist[i4 + 3] = 0;
        if (tid == 0) g_epoch += 1;
    }

    int t  = threadIdx.x;                        // 0..31 local token
    int ty = threadIdx.y;                        // 0..15
    int s  = blockIdx.x * TOK_PER_BLK + t;       // sorted position
    int e4base = blockIdx.y * E4_PER_BLK;        // global float4 offset

    int id = __ldg(&g_sorted[s]).y;

    // Phase 1: gather 4 e4-slots per thread
    #pragma unroll
    for (int i = 0; i < 4; i++) {
        int e4l = ty + 16 * i;                   // 0..63 local
        int e4g = e4base + e4l;
        float4 bv = __ldg((const float4*)b + e4g);
        const float* wp = W + (size_t)(4 * e4g) * VOCAB + id;
        float4 r;
        r.x = (__ldg(wp)                      + bv.x) * SCALE;
        r.y = (__ldg(wp + (size_t)VOCAB)      + bv.y) * SCALE;
        r.z = (__ldg(wp + (size_t)2 * VOCAB)  + bv.z) * SCALE;
        r.w = (__ldg(wp + (size_t)3 * VOCAB)  + bv.w) * SCALE;
        S4[t * S4_PITCH + e4l] = r;
    }

    __syncthreads();

    // Phase 2: token-major coalesced float4 streaming stores
    int tid  = ty * 32 + t;                      // 0..511
    int tl   = tid >> 4;                         // 0..31 local token
    int ey   = tid & 15;                         // 0..15
    int token = __ldg(&g_sorted[blockIdx.x * TOK_PER_BLK + tl]).x;
    float4* outp = (float4*)out + (size_t)token * (EMB / 4) + e4base;
    #pragma unroll
    for (int i = 0; i < 4; i++) {
        int e4l = ey + 16 * i;
        __stcs(&outp[e4l], S4[tl * S4_PITCH + e4l]);
    }
}

extern "C" void kernel_launch(void* const* d_in, const int* in_sizes, int n_in,
                              void* d_out, int out_size)
{
    const int*   ids = (const int*)d_in[0];    // [32768] int32
    const float* W   = (const float*)d_in[1];  // [512*50257]
    const float* b   = (const float*)d_in[2];  // [512]
    float*       out = (float*)d_out;          // [32768*512]

    sort_kernel<<<SORT_BLOCKS, 512>>>(ids);

    dim3 block(32, 16, 1);
    dim3 grid(N_TOKENS / TOK_PER_BLK, EMB / (4 * E4_PER_BLK), 1);  // 1024 x 2
    emb_gather_tr_kernel<<<grid, block>>>(W, b, out);
}